// round 11
// baseline (speedup 1.0000x reference)
#include <cuda_runtime.h>
#include <math.h>

// Problem constants
#define NB   2
#define SS   1024
#define HH   12
#define DD   64
#define NH   (NB*HH)          // 24
#define SPLIT 32              // s-dimension splits for kernel A
#define LB    8               // l-tiles per block in kernel B
#define PV_ELEMS   (NH*DD*DD)         // 24*4096 = 98304
#define PSUM_ELEMS (NH*DD)            // 1536
#define Z_OFF      ((long long)NB*SS*HH*DD*DD)   // 100,663,296
#define Z_COUNT    (NB*SS*HH)                    // 24,576

// Deterministic scratch (no cudaMalloc allowed)
__device__ float g_pv_part[SPLIT * PV_ELEMS];     // 32 * 98304 floats
__device__ float g_psum_part[SPLIT * PSUM_ELEMS]; // 32 * 1536
__device__ float g_pv[PV_ELEMS];
__device__ float g_psum[PSUM_ELEMS];

__device__ __forceinline__ float elu1(float x) {
    return x > 0.0f ? x + 1.0f : __expf(x);
}

// ---------------------------------------------------------------------------
// Kernel A: partial pv[n,h,m,d] = sum_{s in split} p[n,s,h,d]*v[n,s,h,m]
//           partial psum[n,h,d] = sum_{s in split} p[n,s,h,d]
// grid = NH*SPLIT = 768 blocks, 128 threads, 32 s-rows per block.
// FULL prefetch: ALL global loads (both 16-row chunks) issue at the very
// top, before any STS/barrier, so chunk 1 has >1000 cycles of slack.
// Thread (tmy = t>>4 owns 8 m-rows, tdx = t&15 owns a d-quad):
// inner step = 3x LDS.128 + 32 FFMA.
// ---------------------------------------------------------------------------
__global__ __launch_bounds__(128, 5)
void kernelA(const float* __restrict__ v, const float* __restrict__ am,
             const float* __restrict__ hm, const float* __restrict__ pw) {
    int b = blockIdx.x;
    int split = b & (SPLIT - 1);
    int nh    = b >> 5;
    int n = nh / HH, h = nh % HH;
    int s0 = split * (SS / SPLIT);        // 32 rows per block

    int t   = threadIdx.x;
    int tdx = t & 15;     // d-quad index (16 quads of 4)
    int tmy = t >> 4;     // m-octet index (8 octets of 8)

    __shared__ float4 p_s[2][16][16];   // p[buf][s][d-quad]
    __shared__ float4 v_s[2][16][16];   // v[buf][s][m-quad]

    // each thread loads rows r0 (idx t) and r1 (idx t+128) of each chunk
    int r0 = t >> 4,         c0q = t & 15;
    int r1 = (t + 128) >> 4, c1q = t & 15;

    // ---- issue ALL global loads up front (max MLP, single exposure) ----
    int sA0 = s0 + r0,      sA1 = s0 + r1;
    int sB0 = s0 + 16 + r0, sB1 = s0 + 16 + r1;
    float4 vA0  = *(const float4*)(v  + (((size_t)(n*SS + sA0)*HH + h)*DD) + c0q*4);
    float4 vA1  = *(const float4*)(v  + (((size_t)(n*SS + sA1)*HH + h)*DD) + c1q*4);
    float4 vB0  = *(const float4*)(v  + (((size_t)(n*SS + sB0)*HH + h)*DD) + c0q*4);
    float4 vB1  = *(const float4*)(v  + (((size_t)(n*SS + sB1)*HH + h)*DD) + c1q*4);
    float4 pwA0 = *(const float4*)(pw + (size_t)sA0*(HH*DD) + h*DD + c0q*4);
    float4 pwA1 = *(const float4*)(pw + (size_t)sA1*(HH*DD) + h*DD + c1q*4);
    float4 pwB0 = *(const float4*)(pw + (size_t)sB0*(HH*DD) + h*DD + c0q*4);
    float4 pwB1 = *(const float4*)(pw + (size_t)sB1*(HH*DD) + h*DD + c1q*4);
    float  mkA0 = __ldg(am + n*SS + sA0);
    float  mkA1 = __ldg(am + n*SS + sA1);
    float  mkB0 = __ldg(am + n*SS + sB0);
    float  mkB1 = __ldg(am + n*SS + sB1);

    float4 acc[8];
#pragma unroll
    for (int j = 0; j < 8; j++) acc[j] = make_float4(0.f, 0.f, 0.f, 0.f);
    float4 psum_acc = make_float4(0.f, 0.f, 0.f, 0.f);

    // ---- store chunk 0 (elu on arrival) ----
    {
        float4 p4;
        p4.x = elu1(pwA0.x)*mkA0; p4.y = elu1(pwA0.y)*mkA0;
        p4.z = elu1(pwA0.z)*mkA0; p4.w = elu1(pwA0.w)*mkA0;
        p_s[0][r0][c0q] = p4;  v_s[0][r0][c0q] = vA0;
        p4.x = elu1(pwA1.x)*mkA1; p4.y = elu1(pwA1.y)*mkA1;
        p4.z = elu1(pwA1.z)*mkA1; p4.w = elu1(pwA1.w)*mkA1;
        p_s[0][r1][c1q] = p4;  v_s[0][r1][c1q] = vA1;
    }
    __syncthreads();

    // ---- compute chunk 0 ----
#pragma unroll
    for (int ss = 0; ss < 16; ss++) {
        float4 pd = p_s[0][ss][tdx];
        float4 va = v_s[0][ss][tmy*2];
        float4 vb = v_s[0][ss][tmy*2 + 1];
        if (tmy == 0) {
            psum_acc.x += pd.x; psum_acc.y += pd.y;
            psum_acc.z += pd.z; psum_acc.w += pd.w;
        }
        acc[0].x += va.x*pd.x; acc[0].y += va.x*pd.y; acc[0].z += va.x*pd.z; acc[0].w += va.x*pd.w;
        acc[1].x += va.y*pd.x; acc[1].y += va.y*pd.y; acc[1].z += va.y*pd.z; acc[1].w += va.y*pd.w;
        acc[2].x += va.z*pd.x; acc[2].y += va.z*pd.y; acc[2].z += va.z*pd.z; acc[2].w += va.z*pd.w;
        acc[3].x += va.w*pd.x; acc[3].y += va.w*pd.y; acc[3].z += va.w*pd.z; acc[3].w += va.w*pd.w;
        acc[4].x += vb.x*pd.x; acc[4].y += vb.x*pd.y; acc[4].z += vb.x*pd.z; acc[4].w += vb.x*pd.w;
        acc[5].x += vb.y*pd.x; acc[5].y += vb.y*pd.y; acc[5].z += vb.y*pd.z; acc[5].w += vb.y*pd.w;
        acc[6].x += vb.z*pd.x; acc[6].y += vb.z*pd.y; acc[6].z += vb.z*pd.z; acc[6].w += vb.z*pd.w;
        acc[7].x += vb.w*pd.x; acc[7].y += vb.w*pd.y; acc[7].z += vb.w*pd.z; acc[7].w += vb.w*pd.w;
    }

    // ---- store chunk 1 into the other buffer (no WAR on buffer 0) ----
    {
        float4 p4;
        p4.x = elu1(pwB0.x)*mkB0; p4.y = elu1(pwB0.y)*mkB0;
        p4.z = elu1(pwB0.z)*mkB0; p4.w = elu1(pwB0.w)*mkB0;
        p_s[1][r0][c0q] = p4;  v_s[1][r0][c0q] = vB0;
        p4.x = elu1(pwB1.x)*mkB1; p4.y = elu1(pwB1.y)*mkB1;
        p4.z = elu1(pwB1.z)*mkB1; p4.w = elu1(pwB1.w)*mkB1;
        p_s[1][r1][c1q] = p4;  v_s[1][r1][c1q] = vB1;
    }
    __syncthreads();

    // ---- compute chunk 1 ----
#pragma unroll
    for (int ss = 0; ss < 16; ss++) {
        float4 pd = p_s[1][ss][tdx];
        float4 va = v_s[1][ss][tmy*2];
        float4 vb = v_s[1][ss][tmy*2 + 1];
        if (tmy == 0) {
            psum_acc.x += pd.x; psum_acc.y += pd.y;
            psum_acc.z += pd.z; psum_acc.w += pd.w;
        }
        acc[0].x += va.x*pd.x; acc[0].y += va.x*pd.y; acc[0].z += va.x*pd.z; acc[0].w += va.x*pd.w;
        acc[1].x += va.y*pd.x; acc[1].y += va.y*pd.y; acc[1].z += va.y*pd.z; acc[1].w += va.y*pd.w;
        acc[2].x += va.z*pd.x; acc[2].y += va.z*pd.y; acc[2].z += va.z*pd.z; acc[2].w += va.z*pd.w;
        acc[3].x += va.w*pd.x; acc[3].y += va.w*pd.y; acc[3].z += va.w*pd.z; acc[3].w += va.w*pd.w;
        acc[4].x += vb.x*pd.x; acc[4].y += vb.x*pd.y; acc[4].z += vb.x*pd.z; acc[4].w += vb.x*pd.w;
        acc[5].x += vb.y*pd.x; acc[5].y += vb.y*pd.y; acc[5].z += vb.y*pd.z; acc[5].w += vb.y*pd.w;
        acc[6].x += vb.z*pd.x; acc[6].y += vb.z*pd.y; acc[6].z += vb.z*pd.z; acc[6].w += vb.z*pd.w;
        acc[7].x += vb.w*pd.x; acc[7].y += vb.w*pd.y; acc[7].z += vb.w*pd.z; acc[7].w += vb.w*pd.w;
    }

    float hmv = __ldg(hm + h);
    float* dst = g_pv_part + (size_t)split * PV_ELEMS + nh * (DD*DD);
#pragma unroll
    for (int j = 0; j < 8; j++) {
        float4 o;
        o.x = acc[j].x * hmv; o.y = acc[j].y * hmv;
        o.z = acc[j].z * hmv; o.w = acc[j].w * hmv;
        *(float4*)(dst + (tmy*8 + j)*DD + tdx*4) = o;
    }
    if (tmy == 0) {
        *(float4*)(g_psum_part + (size_t)split * PSUM_ELEMS + nh*DD + tdx*4) = psum_acc;
    }
}

// ---------------------------------------------------------------------------
// Kernel A2: reduce the SPLIT partials. Float granularity for parallelism
// (390 blocks); consecutive threads read consecutive floats (coalesced),
// 32 independent loads per thread (full MLP).
// ---------------------------------------------------------------------------
__global__ void kernelA2() {
    int gid = blockIdx.x * 256 + threadIdx.x;
    if (gid < PV_ELEMS) {
        float s = 0.f;
#pragma unroll
        for (int k = 0; k < SPLIT; k++)
            s += g_pv_part[(size_t)k * PV_ELEMS + gid];
        g_pv[gid] = s;
    } else if (gid < PV_ELEMS + PSUM_ELEMS) {
        int i = gid - PV_ELEMS;
        float s = 0.f;
#pragma unroll
        for (int k = 0; k < SPLIT; k++)
            s += g_psum_part[(size_t)k * PSUM_ELEMS + i];
        g_psum[i] = s;
    }
}

// ---------------------------------------------------------------------------
// Kernel B: stream the output.
//  ppv[n,l,h,m,d] = p[n,l,h,d] * pv[n,h,m,d]
//  z_pp[n,l,h]    = sum_d p[n,l,h,d]*psum[n,h,d] + eps
// grid = NH * (SS/LB) = 3072 blocks, 256 threads, 4 CTAs/SM (32 warps).
// Prologue: load pv tile + psum + ALL 8 p vectors (one latency exposure),
// reduce z. Streaming loop: pl in registers, pv via LDS (idle pipe during
// the store stream), no barriers.
// ---------------------------------------------------------------------------
__global__ __launch_bounds__(256, 4)
void kernelB(const float* __restrict__ am, const float* __restrict__ pw,
             float* __restrict__ out, int write_z) {
    __shared__ float pv_s[DD*DD];
    __shared__ float psum_s[DD];
    __shared__ float p_all[LB*DD];     // 8 p vectors
    __shared__ float red_all[LB*DD];   // p*psum for z reduction

    int b  = blockIdx.x;
    int lc = b & (SS/LB - 1);     // 0..127
    int nh = b >> 7;
    int n = nh / HH, h = nh % HH;
    int t = threadIdx.x;

    float4* pv4 = (float4*)pv_s;
    const float4* gpv4 = (const float4*)g_pv + (size_t)nh * (DD*DD/4);
#pragma unroll
    for (int i = 0; i < 4; i++) pv4[t + i*256] = gpv4[t + i*256];
    if (t < DD/4) ((float4*)psum_s)[t] = ((const float4*)g_psum)[nh*(DD/4) + t];
    __syncthreads();

    // All LB p vectors in one shot: 512 elements, 2 per thread
#pragma unroll
    for (int i = 0; i < 2; i++) {
        int idx = t + i*256;
        int li  = idx >> 6;
        int d   = idx & 63;
        int l   = lc * LB + li;
        float x   = pw[(size_t)l*(HH*DD) + h*DD + d];
        float val = elu1(x) * __ldg(am + n*SS + l);
        p_all[idx]   = val;
        red_all[idx] = val * psum_s[d];
    }
    __syncthreads();

    // z_pp: warp w reduces l-tile w
    if (write_z) {
        int w = t >> 5, lane = t & 31;
        float s = red_all[w*64 + lane] + red_all[w*64 + 32 + lane];
#pragma unroll
        for (int off = 16; off > 0; off >>= 1)
            s += __shfl_down_sync(0xFFFFFFFFu, s, off);
        if (lane == 0)
            out[Z_OFF + (size_t)(n*SS + lc*LB + w)*HH + h] = s + 1e-6f;
    }

    // pl in registers (depends only on li and t&15); pv read per-iter via
    // LDS (keeps regs <= 64 for 4 CTAs/SM). 32 streaming stores per thread.
    float4 pl[LB];
#pragma unroll
    for (int li = 0; li < LB; li++)
        pl[li] = ((float4*)p_all)[li*16 + (t & 15)];

#pragma unroll
    for (int li = 0; li < LB; li++) {
        size_t base4 = ((size_t)((n*SS + lc*LB + li)*HH + h)) * (DD*DD/4);
        float4* o4 = (float4*)out + base4;
#pragma unroll
        for (int i = 0; i < 4; i++) {
            float4 pvv = pv4[t + i*256];
            float4 r;
            r.x = pvv.x * pl[li].x;
            r.y = pvv.y * pl[li].y;
            r.z = pvv.z * pl[li].z;
            r.w = pvv.w * pl[li].w;
            __stcs(o4 + t + i*256, r);
        }
    }
}

// ---------------------------------------------------------------------------
// Launch. Inputs (metadata order): q, v, attention_mask, head_mask, pos_weight.
// q is unused by the math (only its shape matters in the reference).
// Output: ppv (N*S*H*D*D floats) followed by z_pp (N*S*H floats).
// ---------------------------------------------------------------------------
extern "C" void kernel_launch(void* const* d_in, const int* in_sizes, int n_in,
                              void* d_out, int out_size) {
    const float* v  = (const float*)d_in[1];
    const float* am = (const float*)d_in[2];
    const float* hm = (const float*)d_in[3];
    const float* pw = (const float*)d_in[4];
    float* out = (float*)d_out;

    int write_z = (long long)out_size >= Z_OFF + Z_COUNT;

    kernelA<<<NH * SPLIT, 128>>>(v, am, hm, pw);
    int totalA2 = PV_ELEMS + PSUM_ELEMS;             // 99840
    kernelA2<<<(totalA2 + 255) / 256, 256>>>();
    kernelB<<<NH * (SS/LB), 256>>>(am, pw, out, write_z);
}